// round 1
// baseline (speedup 1.0000x reference)
#include <cuda_runtime.h>
#include <math.h>

// Problem constants: B=16, S=1024, D=1024, H=16, Dh=64
constexpr int Bn = 16;
constexpr int Sn = 1024;
constexpr int Dn = 1024;
constexpr int Hn = 16;
constexpr int DhN = 64;

// Scratch Q/K/V in [B,H,S,Dh] layout, 64MB each (device globals: allowed scratch)
__device__ float g_q[(size_t)Bn * Hn * Sn * DhN];
__device__ float g_k[(size_t)Bn * Hn * Sn * DhN];
__device__ float g_v[(size_t)Bn * Hn * Sn * DhN];

// ---------------------------------------------------------------------------
// NT-GEMM with fused bias + head-split scatter.
//   A: [M=16384, K=1024] row-major (hidden states, rows = b*S+s)
//   W: [N=1024, K=1024]  row-major (torch Linear weight; y = x @ W^T + b)
//   out: [B, H, S, Dh]   out[((b*H+h)*S + s)*Dh + dh], n = h*64+dh
// Block tile 128x128, BK=16, thread tile 8x8, 256 threads.
// ---------------------------------------------------------------------------
__global__ __launch_bounds__(256) void qkv_gemm(
    const float* __restrict__ A,
    const float* __restrict__ W,
    const float* __restrict__ bias,
    float* __restrict__ out)
{
    constexpr int K = 1024;
    constexpr int BM = 128, BN = 128, BK = 16, TM = 8, TN = 8;
    __shared__ float As[BK][BM + 4];  // stride 132: float4-aligned, 2-way store conflict only
    __shared__ float Ws[BK][BN + 4];

    const int tid  = threadIdx.x;
    const int tRow = tid >> 4;   // 0..15
    const int tCol = tid & 15;   // 0..15
    const int m0 = blockIdx.y * BM;
    const int n0 = blockIdx.x * BN;

    const int loadRow = tid >> 2;        // 0..63
    const int loadCol = (tid & 3) << 2;  // 0,4,8,12

    const float* Ap = A + (size_t)m0 * K;
    const float* Wp = W + (size_t)n0 * K;

    float acc[TM][TN];
#pragma unroll
    for (int i = 0; i < TM; i++)
#pragma unroll
        for (int j = 0; j < TN; j++) acc[i][j] = 0.f;

    for (int k0 = 0; k0 < K; k0 += BK) {
#pragma unroll
        for (int rr = 0; rr < 2; rr++) {
            const int row = loadRow + rr * 64;
            float4 a = *reinterpret_cast<const float4*>(Ap + (size_t)row * K + k0 + loadCol);
            As[loadCol + 0][row] = a.x;
            As[loadCol + 1][row] = a.y;
            As[loadCol + 2][row] = a.z;
            As[loadCol + 3][row] = a.w;
            float4 w = *reinterpret_cast<const float4*>(Wp + (size_t)row * K + k0 + loadCol);
            Ws[loadCol + 0][row] = w.x;
            Ws[loadCol + 1][row] = w.y;
            Ws[loadCol + 2][row] = w.z;
            Ws[loadCol + 3][row] = w.w;
        }
        __syncthreads();

#pragma unroll
        for (int k = 0; k < BK; k++) {
            float regM[TM], regN[TN];
#pragma unroll
            for (int i = 0; i < TM; i++) regM[i] = As[k][tRow * TM + i];
#pragma unroll
            for (int j = 0; j < TN; j++) regN[j] = Ws[k][tCol * TN + j];
#pragma unroll
            for (int i = 0; i < TM; i++)
#pragma unroll
                for (int j = 0; j < TN; j++)
                    acc[i][j] = fmaf(regM[i], regN[j], acc[i][j]);
        }
        __syncthreads();
    }

    // Epilogue: + bias, scatter to [B,H,S,Dh]
#pragma unroll
    for (int i = 0; i < TM; i++) {
        const int m  = m0 + tRow * TM + i;
        const int bb = m >> 10;       // batch
        const int s  = m & 1023;      // seq
#pragma unroll
        for (int jj = 0; jj < TN; jj += 4) {
            const int n  = n0 + tCol * TN + jj;
            const int h  = n >> 6;
            const int dh = n & 63;
            float4 r;
            r.x = acc[i][jj + 0] + __ldg(&bias[n + 0]);
            r.y = acc[i][jj + 1] + __ldg(&bias[n + 1]);
            r.z = acc[i][jj + 2] + __ldg(&bias[n + 2]);
            r.w = acc[i][jj + 3] + __ldg(&bias[n + 3]);
            // (b*H+h)*S*Dh = (bb*16+h)<<16 ; s*Dh = s<<6
            *reinterpret_cast<float4*>(
                out + (((size_t)(bb * 16 + h)) << 16) + ((size_t)s << 6) + dh) = r;
        }
    }
}

// ---------------------------------------------------------------------------
// Flash-attention style kernel. One block = 64 query rows of one (b,h).
// Thread (r, c4): r = tid/4 owns query row r, c4 = tid%4 owns a column quad.
//   Score phase: 8 score columns (c = c4*8+j) per thread over BC=32 keys.
//   PV phase:    16 output dims  (d = c4*16+j) per thread.
// Online softmax state per row shared across the 4 lanes via shfl (width 4).
// smem: Qs[64][65], Ks[d][c]=[64][32], Vs[c][d]=[32][64], Ps[64][33] = 40.5 KB
// ---------------------------------------------------------------------------
__global__ __launch_bounds__(256) void attn_kernel(
    const float* __restrict__ Qg,
    const float* __restrict__ Kg,
    const float* __restrict__ Vg,
    float* __restrict__ out)
{
    constexpr int BR = 64, BC = 32, D = DhN;
    __shared__ float Qs[BR * 65];
    __shared__ float Ks[D * BC];   // [d][c]
    __shared__ float Vs[BC * D];   // [c][d]
    __shared__ float Ps[BR * 33];

    const int tid = threadIdx.x;
    const int r   = tid >> 2;   // 0..63 query row
    const int c4  = tid & 3;    // 0..3 column quad

    const int bh = blockIdx.y;          // b*16 + h
    const int q0 = blockIdx.x * BR;

    const float* Qp = Qg + ((size_t)bh << 16) + (size_t)q0 * D;
    const float* Kp = Kg + ((size_t)bh << 16);
    const float* Vp = Vg + ((size_t)bh << 16);

    // Load Q tile (row-major, pad-65)
    {
        const int row  = tid >> 2;
        const int quad = tid & 3;
#pragma unroll
        for (int i = 0; i < 4; i++) {
            const int d = quad * 16 + i * 4;
            float4 v = *reinterpret_cast<const float4*>(Qp + (size_t)row * D + d);
            Qs[row * 65 + d + 0] = v.x;
            Qs[row * 65 + d + 1] = v.y;
            Qs[row * 65 + d + 2] = v.z;
            Qs[row * 65 + d + 3] = v.w;
        }
    }

    float m = -1e30f, l = 0.f;
    float O[16];
#pragma unroll
    for (int i = 0; i < 16; i++) O[i] = 0.f;

    for (int t = 0; t < Sn / BC; t++) {
        __syncthreads();  // prior PV done: safe to overwrite Ks/Vs

        // Load K tile transposed: Ks[d][c] = K[t*BC + c][d]
        {
            const int c    = tid >> 3;  // 0..31
            const int part = tid & 7;   // 0..7
#pragma unroll
            for (int i = 0; i < 2; i++) {
                const int d = part * 8 + i * 4;
                float4 v = *reinterpret_cast<const float4*>(
                    Kp + (size_t)(t * BC + c) * D + d);
                Ks[(d + 0) * BC + c] = v.x;
                Ks[(d + 1) * BC + c] = v.y;
                Ks[(d + 2) * BC + c] = v.z;
                Ks[(d + 3) * BC + c] = v.w;
            }
        }
        // Load V tile flat (tile is contiguous in global)
        {
            const float4* src = reinterpret_cast<const float4*>(Vp + (size_t)t * BC * D);
            float4* dst = reinterpret_cast<float4*>(Vs);
            dst[tid]       = src[tid];
            dst[tid + 256] = src[tid + 256];
        }
        __syncthreads();

        // Scores: s[j] = Q[r,:] . K[c4*8+j,:]
        float s[8];
#pragma unroll
        for (int j = 0; j < 8; j++) s[j] = 0.f;
#pragma unroll 8
        for (int d = 0; d < D; d++) {
            const float qv = Qs[r * 65 + d];
            const float4 k0 = *reinterpret_cast<const float4*>(&Ks[d * BC + c4 * 8]);
            const float4 k1 = *reinterpret_cast<const float4*>(&Ks[d * BC + c4 * 8 + 4]);
            s[0] = fmaf(qv, k0.x, s[0]);
            s[1] = fmaf(qv, k0.y, s[1]);
            s[2] = fmaf(qv, k0.z, s[2]);
            s[3] = fmaf(qv, k0.w, s[3]);
            s[4] = fmaf(qv, k1.x, s[4]);
            s[5] = fmaf(qv, k1.y, s[5]);
            s[6] = fmaf(qv, k1.z, s[6]);
            s[7] = fmaf(qv, k1.w, s[7]);
        }

        constexpr float scale = 0.125f;  // 1/sqrt(64)
        float mt = -1e30f;
#pragma unroll
        for (int j = 0; j < 8; j++) {
            s[j] *= scale;
            mt = fmaxf(mt, s[j]);
        }
        mt = fmaxf(mt, __shfl_xor_sync(0xffffffffu, mt, 1));
        mt = fmaxf(mt, __shfl_xor_sync(0xffffffffu, mt, 2));

        const float mn    = fmaxf(m, mt);
        const float alpha = __expf(m - mn);
        float ls = 0.f;
#pragma unroll
        for (int j = 0; j < 8; j++) {
            const float p = __expf(s[j] - mn);
            ls += p;
            Ps[r * 33 + c4 * 8 + j] = p;
        }
        ls += __shfl_xor_sync(0xffffffffu, ls, 1);
        ls += __shfl_xor_sync(0xffffffffu, ls, 2);
        l = alpha * l + ls;
        m = mn;
#pragma unroll
        for (int i = 0; i < 16; i++) O[i] *= alpha;
        __syncthreads();

        // PV: O[d] += sum_kk P[r][kk] * V[kk][d],  d = c4*16 + j
#pragma unroll 4
        for (int kk = 0; kk < BC; kk++) {
            const float p = Ps[r * 33 + kk];
            const float4 v0 = *reinterpret_cast<const float4*>(&Vs[kk * D + c4 * 16 + 0]);
            const float4 v1 = *reinterpret_cast<const float4*>(&Vs[kk * D + c4 * 16 + 4]);
            const float4 v2 = *reinterpret_cast<const float4*>(&Vs[kk * D + c4 * 16 + 8]);
            const float4 v3 = *reinterpret_cast<const float4*>(&Vs[kk * D + c4 * 16 + 12]);
            O[0]  = fmaf(p, v0.x, O[0]);
            O[1]  = fmaf(p, v0.y, O[1]);
            O[2]  = fmaf(p, v0.z, O[2]);
            O[3]  = fmaf(p, v0.w, O[3]);
            O[4]  = fmaf(p, v1.x, O[4]);
            O[5]  = fmaf(p, v1.y, O[5]);
            O[6]  = fmaf(p, v1.z, O[6]);
            O[7]  = fmaf(p, v1.w, O[7]);
            O[8]  = fmaf(p, v2.x, O[8]);
            O[9]  = fmaf(p, v2.y, O[9]);
            O[10] = fmaf(p, v2.z, O[10]);
            O[11] = fmaf(p, v2.w, O[11]);
            O[12] = fmaf(p, v3.x, O[12]);
            O[13] = fmaf(p, v3.y, O[13]);
            O[14] = fmaf(p, v3.z, O[14]);
            O[15] = fmaf(p, v3.w, O[15]);
        }
    }

    // Final: normalize and write to out[B,S,H*Dh]
    const float inv = 1.0f / l;
    const int b = bh >> 4;
    const int h = bh & 15;
    float* op = out + (size_t)(b * Sn + q0 + r) * Dn + h * DhN + c4 * 16;
#pragma unroll
    for (int u = 0; u < 4; u++) {
        float4 v;
        v.x = O[4 * u + 0] * inv;
        v.y = O[4 * u + 1] * inv;
        v.z = O[4 * u + 2] * inv;
        v.w = O[4 * u + 3] * inv;
        *reinterpret_cast<float4*>(op + 4 * u) = v;
    }
}

// ---------------------------------------------------------------------------
extern "C" void kernel_launch(void* const* d_in, const int* in_sizes, int n_in,
                              void* d_out, int out_size)
{
    const float* X  = (const float*)d_in[0];
    const float* Wq = (const float*)d_in[1];
    const float* bq = (const float*)d_in[2];
    const float* Wk = (const float*)d_in[3];
    const float* bk = (const float*)d_in[4];
    const float* Wv = (const float*)d_in[5];
    const float* bv = (const float*)d_in[6];
    float* out = (float*)d_out;

    float *q, *k, *v;
    cudaGetSymbolAddress((void**)&q, g_q);
    cudaGetSymbolAddress((void**)&k, g_k);
    cudaGetSymbolAddress((void**)&v, g_v);

    const dim3 gemm_grid(Dn / 128, (Bn * Sn) / 128);  // (8, 128)
    qkv_gemm<<<gemm_grid, 256>>>(X, Wq, bq, q);
    qkv_gemm<<<gemm_grid, 256>>>(X, Wk, bk, k);
    qkv_gemm<<<gemm_grid, 256>>>(X, Wv, bv, v);

    const dim3 attn_grid(Sn / 64, Bn * Hn);           // (16, 256)
    attn_kernel<<<attn_grid, 256>>>(q, k, v, out);
}

// round 2
// speedup vs baseline: 2.1912x; 2.1912x over previous
#include <cuda_runtime.h>
#include <math.h>

// Problem constants: B=16, S=1024, D=1024, H=16, Dh=64
constexpr int Bn = 16;
constexpr int Sn = 1024;
constexpr int Dn = 1024;
constexpr int Hn = 16;
constexpr int DhN = 64;

// Scratch Q/K/V in [B,H,S,Dh] layout (device globals: allowed scratch)
__device__ float g_q[(size_t)Bn * Hn * Sn * DhN];
__device__ float g_k[(size_t)Bn * Hn * Sn * DhN];
__device__ float g_v[(size_t)Bn * Hn * Sn * DhN];

// ---------------------------------------------------------------------------
// NT-GEMM with fused bias + head-split scatter (unchanged from R1).
// ---------------------------------------------------------------------------
__global__ __launch_bounds__(256) void qkv_gemm(
    const float* __restrict__ A,
    const float* __restrict__ W,
    const float* __restrict__ bias,
    float* __restrict__ out)
{
    constexpr int K = 1024;
    constexpr int BM = 128, BN = 128, BK = 16, TM = 8, TN = 8;
    __shared__ float As[BK][BM + 4];
    __shared__ float Ws[BK][BN + 4];

    const int tid  = threadIdx.x;
    const int tRow = tid >> 4;
    const int tCol = tid & 15;
    const int m0 = blockIdx.y * BM;
    const int n0 = blockIdx.x * BN;

    const int loadRow = tid >> 2;
    const int loadCol = (tid & 3) << 2;

    const float* Ap = A + (size_t)m0 * K;
    const float* Wp = W + (size_t)n0 * K;

    float acc[TM][TN];
#pragma unroll
    for (int i = 0; i < TM; i++)
#pragma unroll
        for (int j = 0; j < TN; j++) acc[i][j] = 0.f;

    for (int k0 = 0; k0 < K; k0 += BK) {
#pragma unroll
        for (int rr = 0; rr < 2; rr++) {
            const int row = loadRow + rr * 64;
            float4 a = *reinterpret_cast<const float4*>(Ap + (size_t)row * K + k0 + loadCol);
            As[loadCol + 0][row] = a.x;
            As[loadCol + 1][row] = a.y;
            As[loadCol + 2][row] = a.z;
            As[loadCol + 3][row] = a.w;
            float4 w = *reinterpret_cast<const float4*>(Wp + (size_t)row * K + k0 + loadCol);
            Ws[loadCol + 0][row] = w.x;
            Ws[loadCol + 1][row] = w.y;
            Ws[loadCol + 2][row] = w.z;
            Ws[loadCol + 3][row] = w.w;
        }
        __syncthreads();

#pragma unroll
        for (int k = 0; k < BK; k++) {
            float regM[TM], regN[TN];
#pragma unroll
            for (int i = 0; i < TM; i++) regM[i] = As[k][tRow * TM + i];
#pragma unroll
            for (int j = 0; j < TN; j++) regN[j] = Ws[k][tCol * TN + j];
#pragma unroll
            for (int i = 0; i < TM; i++)
#pragma unroll
                for (int j = 0; j < TN; j++)
                    acc[i][j] = fmaf(regM[i], regN[j], acc[i][j]);
        }
        __syncthreads();
    }

#pragma unroll
    for (int i = 0; i < TM; i++) {
        const int m  = m0 + tRow * TM + i;
        const int bb = m >> 10;
        const int s  = m & 1023;
#pragma unroll
        for (int jj = 0; jj < TN; jj += 4) {
            const int n  = n0 + tCol * TN + jj;
            const int h  = n >> 6;
            const int dh = n & 63;
            float4 r;
            r.x = acc[i][jj + 0] + __ldg(&bias[n + 0]);
            r.y = acc[i][jj + 1] + __ldg(&bias[n + 1]);
            r.z = acc[i][jj + 2] + __ldg(&bias[n + 2]);
            r.w = acc[i][jj + 3] + __ldg(&bias[n + 3]);
            *reinterpret_cast<float4*>(
                out + (((size_t)(bb * 16 + h)) << 16) + ((size_t)s << 6) + dh) = r;
        }
    }
}

// ---------------------------------------------------------------------------
// Flash attention, register-blocked 8x8 per thread.
//   Block: 128 threads = 16x8 grid (tRow 0..15, tCol 0..7).
//   BR=128 query rows, BC=64 key tile, Dh=64.
//   Thread owns score tile rows tRow*8..+7, cols {4*tCol+j} u {32+4*tCol+j};
//   output tile rows same, dh cols same pattern.
// smem (dynamic 96KB):
//   Qs: Q^T [d=64][r=128], XOR-swizzled float4 groups (32 groups/row)
//   Ks: K^T [d=64][c=64],  swizzled (16 groups/row)
//   Vs: V   [c=64][d=64],  natural
//   Ps: P^T [c=64][r=128], swizzled
// Swizzle: element (row rr, col x) of a [rr][X] tile lives at
//   rr*X + 4*((x>>2) ^ (rr>>2)) + (x&3)   -> conflict-free vector reads.
// ---------------------------------------------------------------------------
__global__ __launch_bounds__(128) void attn_kernel(
    const float* __restrict__ Qg,
    const float* __restrict__ Kg,
    const float* __restrict__ Vg,
    float* __restrict__ out)
{
    extern __shared__ float sm[];
    float* Qs = sm;                  // 64*128 = 8192 floats
    float* Ks = sm + 64 * 128;       // 64*64  = 4096
    float* Vs = Ks + 64 * 64;        // 64*64  = 4096
    float* Ps = Vs + 64 * 64;        // 64*128 = 8192

    const int tid  = threadIdx.x;
    const int tRow = tid >> 3;   // 0..15
    const int tCol = tid & 7;    // 0..7

    const int bh = blockIdx.y;           // b*16 + h
    const int q0 = blockIdx.x * 128;

    const float* Qp = Qg + ((size_t)bh << 16) + (size_t)q0 * 64;
    const float* Kp = Kg + ((size_t)bh << 16);
    const float* Vp = Vg + ((size_t)bh << 16);

    // ---- Load Q tile transposed + swizzled (once per block) ----
    {
        const int rl = tid >> 4;     // 0..7
        const int gq = tid & 15;     // float4 group along d
#pragma unroll
        for (int rep = 0; rep < 16; rep++) {
            const int r = rl + rep * 8;
            float4 v = *reinterpret_cast<const float4*>(Qp + (size_t)r * 64 + gq * 4);
            const int sw = ((((r >> 2) ^ gq) & 31) << 2) + (r & 3);
            Qs[(4 * gq + 0) * 128 + sw] = v.x;
            Qs[(4 * gq + 1) * 128 + sw] = v.y;
            Qs[(4 * gq + 2) * 128 + sw] = v.z;
            Qs[(4 * gq + 3) * 128 + sw] = v.w;
        }
    }

    float m_[8], l_[8];
    float O[8][8];
#pragma unroll
    for (int i = 0; i < 8; i++) {
        m_[i] = -1e30f;
        l_[i] = 0.f;
#pragma unroll
        for (int j = 0; j < 8; j++) O[i][j] = 0.f;
    }

    for (int t = 0; t < Sn / 64; t++) {
        __syncthreads();  // previous PV done: safe to overwrite Ks/Vs

        // ---- Load K^T (swizzled) and V (natural) tiles ----
        {
            const int cl = tid >> 4;     // 0..7
            const int gk = tid & 15;
#pragma unroll
            for (int rep = 0; rep < 8; rep++) {
                const int c = cl + rep * 8;
                const float4 kv = *reinterpret_cast<const float4*>(
                    Kp + (size_t)(t * 64 + c) * 64 + gk * 4);
                const int sw = ((((c >> 2) ^ gk) & 15) << 2) + (c & 3);
                Ks[(4 * gk + 0) * 64 + sw] = kv.x;
                Ks[(4 * gk + 1) * 64 + sw] = kv.y;
                Ks[(4 * gk + 2) * 64 + sw] = kv.z;
                Ks[(4 * gk + 3) * 64 + sw] = kv.w;
                const float4 vv = *reinterpret_cast<const float4*>(
                    Vp + (size_t)(t * 64 + c) * 64 + gk * 4);
                *reinterpret_cast<float4*>(Vs + c * 64 + gk * 4) = vv;
            }
        }
        __syncthreads();

        // ---- Score GEMM: s[8][8] = Q[rows] . K[cols] over d=64 ----
        float s[8][8];
#pragma unroll
        for (int i = 0; i < 8; i++)
#pragma unroll
            for (int j = 0; j < 8; j++) s[i][j] = 0.f;

        for (int k4 = 0; k4 < 16; k4++) {
            const float* qb = Qs + k4 * 4 * 128;
            const float* kb = Ks + k4 * 4 * 64;
            const int gq0 = (((2 * tRow) ^ k4) & 31) << 2;
            const int gq1 = (((2 * tRow + 1) ^ k4) & 31) << 2;
            const int gk0 = ((tCol ^ k4) & 15) << 2;
            const int gk1 = (((tCol + 8) ^ k4) & 15) << 2;
#pragma unroll
            for (int kk = 0; kk < 4; kk++) {
                const float4 a0 = *reinterpret_cast<const float4*>(qb + kk * 128 + gq0);
                const float4 a1 = *reinterpret_cast<const float4*>(qb + kk * 128 + gq1);
                const float4 b0 = *reinterpret_cast<const float4*>(kb + kk * 64 + gk0);
                const float4 b1 = *reinterpret_cast<const float4*>(kb + kk * 64 + gk1);
                const float am[8] = {a0.x, a0.y, a0.z, a0.w, a1.x, a1.y, a1.z, a1.w};
                const float bn[8] = {b0.x, b0.y, b0.z, b0.w, b1.x, b1.y, b1.z, b1.w};
#pragma unroll
                for (int i = 0; i < 8; i++)
#pragma unroll
                    for (int j = 0; j < 8; j++)
                        s[i][j] = fmaf(am[i], bn[j], s[i][j]);
            }
        }

        // ---- Online softmax (rows replicated across the 8 tCol lanes) ----
        constexpr float scale = 0.125f;   // 1/sqrt(64)
#pragma unroll
        for (int i = 0; i < 8; i++) {
            float mt = -1e30f;
#pragma unroll
            for (int j = 0; j < 8; j++) {
                s[i][j] *= scale;
                mt = fmaxf(mt, s[i][j]);
            }
            mt = fmaxf(mt, __shfl_xor_sync(0xffffffffu, mt, 1));
            mt = fmaxf(mt, __shfl_xor_sync(0xffffffffu, mt, 2));
            mt = fmaxf(mt, __shfl_xor_sync(0xffffffffu, mt, 4));

            const float mn    = fmaxf(m_[i], mt);
            const float alpha = __expf(m_[i] - mn);
            float ls = 0.f;
#pragma unroll
            for (int j = 0; j < 8; j++) {
                s[i][j] = __expf(s[i][j] - mn);
                ls += s[i][j];
            }
            ls += __shfl_xor_sync(0xffffffffu, ls, 1);
            ls += __shfl_xor_sync(0xffffffffu, ls, 2);
            ls += __shfl_xor_sync(0xffffffffu, ls, 4);
            l_[i] = alpha * l_[i] + ls;
            m_[i] = mn;
#pragma unroll
            for (int j = 0; j < 8; j++) O[i][j] *= alpha;
        }

        // ---- Store P^T (swizzled) ----
#pragma unroll
        for (int jj = 0; jj < 8; jj++) {
            const int c  = (jj < 4) ? (tCol * 4 + jj) : (32 + tCol * 4 + (jj - 4));
            const int f3 = c >> 2;
            const float4 p0 = make_float4(s[0][jj], s[1][jj], s[2][jj], s[3][jj]);
            const float4 p1 = make_float4(s[4][jj], s[5][jj], s[6][jj], s[7][jj]);
            *reinterpret_cast<float4*>(
                Ps + c * 128 + ((((2 * tRow) ^ f3) & 31) << 2)) = p0;
            *reinterpret_cast<float4*>(
                Ps + c * 128 + ((((2 * tRow + 1) ^ f3) & 31) << 2)) = p1;
        }
        __syncthreads();

        // ---- PV GEMM: O[8][8] += P[rows][c] * V[c][dh] over c=64 ----
        for (int c4 = 0; c4 < 16; c4++) {
            const float* pb = Ps + c4 * 4 * 128;
            const float* vb = Vs + c4 * 4 * 64;
            const int gp0 = (((2 * tRow) ^ c4) & 31) << 2;
            const int gp1 = (((2 * tRow + 1) ^ c4) & 31) << 2;
#pragma unroll
            for (int cc = 0; cc < 4; cc++) {
                const float4 p0 = *reinterpret_cast<const float4*>(pb + cc * 128 + gp0);
                const float4 p1 = *reinterpret_cast<const float4*>(pb + cc * 128 + gp1);
                const float4 v0 = *reinterpret_cast<const float4*>(vb + cc * 64 + tCol * 4);
                const float4 v1 = *reinterpret_cast<const float4*>(vb + cc * 64 + 32 + tCol * 4);
                const float pm[8] = {p0.x, p0.y, p0.z, p0.w, p1.x, p1.y, p1.z, p1.w};
                const float vn[8] = {v0.x, v0.y, v0.z, v0.w, v1.x, v1.y, v1.z, v1.w};
#pragma unroll
                for (int i = 0; i < 8; i++)
#pragma unroll
                    for (int j = 0; j < 8; j++)
                        O[i][j] = fmaf(pm[i], vn[j], O[i][j]);
            }
        }
    }

    // ---- Epilogue: normalize, write to out[B,S,H*Dh] ----
    const int b = bh >> 4;
    const int h = bh & 15;
#pragma unroll
    for (int i = 0; i < 8; i++) {
        const float inv = 1.0f / l_[i];
        const int row = q0 + tRow * 8 + i;
        float* op = out + (size_t)(b * Sn + row) * Dn + h * DhN;
        float4 o0, o1;
        o0.x = O[i][0] * inv; o0.y = O[i][1] * inv;
        o0.z = O[i][2] * inv; o0.w = O[i][3] * inv;
        o1.x = O[i][4] * inv; o1.y = O[i][5] * inv;
        o1.z = O[i][6] * inv; o1.w = O[i][7] * inv;
        *reinterpret_cast<float4*>(op + tCol * 4) = o0;
        *reinterpret_cast<float4*>(op + 32 + tCol * 4) = o1;
    }
}

// ---------------------------------------------------------------------------
extern "C" void kernel_launch(void* const* d_in, const int* in_sizes, int n_in,
                              void* d_out, int out_size)
{
    const float* X  = (const float*)d_in[0];
    const float* Wq = (const float*)d_in[1];
    const float* bq = (const float*)d_in[2];
    const float* Wk = (const float*)d_in[3];
    const float* bk = (const float*)d_in[4];
    const float* Wv = (const float*)d_in[5];
    const float* bv = (const float*)d_in[6];
    float* out = (float*)d_out;

    float *q, *k, *v;
    cudaGetSymbolAddress((void**)&q, g_q);
    cudaGetSymbolAddress((void**)&k, g_k);
    cudaGetSymbolAddress((void**)&v, g_v);

    const dim3 gemm_grid(Dn / 128, (Bn * Sn) / 128);  // (8, 128)
    qkv_gemm<<<gemm_grid, 256>>>(X, Wq, bq, q);
    qkv_gemm<<<gemm_grid, 256>>>(X, Wk, bk, k);
    qkv_gemm<<<gemm_grid, 256>>>(X, Wv, bv, v);

    const int smem_bytes = 96 * 1024;
    cudaFuncSetAttribute(attn_kernel,
                         cudaFuncAttributeMaxDynamicSharedMemorySize, smem_bytes);
    const dim3 attn_grid(Sn / 128, Bn * Hn);          // (8, 256)
    attn_kernel<<<attn_grid, 128, smem_bytes>>>(q, k, v, out);
}

// round 4
// speedup vs baseline: 3.9020x; 1.7808x over previous
#include <cuda_runtime.h>
#include <math.h>
#include <cstdint>

// Problem constants: B=16, S=1024, D=1024, H=16, Dh=64
constexpr int Bn = 16;
constexpr int Sn = 1024;
constexpr int Dn = 1024;
constexpr int Hn = 16;
constexpr int DhN = 64;

// Scratch Q/K/V in [B,H,S,Dh] layout (device globals: allowed scratch)
__device__ float g_q[(size_t)Bn * Hn * Sn * DhN];
__device__ float g_k[(size_t)Bn * Hn * Sn * DhN];
__device__ float g_v[(size_t)Bn * Hn * Sn * DhN];

// ===========================================================================
// mma.sync tf32 helpers (arch-independent PTX, works on plain compute_103)
// ===========================================================================
__device__ __forceinline__ void mma_tf32_16x8x8(
    float& d0, float& d1, float& d2, float& d3,
    uint32_t a0, uint32_t a1, uint32_t a2, uint32_t a3,
    uint32_t b0, uint32_t b1)
{
    asm volatile(
        "mma.sync.aligned.m16n8k8.row.col.f32.tf32.tf32.f32 "
        "{%0,%1,%2,%3}, {%4,%5,%6,%7}, {%8,%9}, {%0,%1,%2,%3};"
        : "+f"(d0), "+f"(d1), "+f"(d2), "+f"(d3)
        : "r"(a0), "r"(a1), "r"(a2), "r"(a3), "r"(b0), "r"(b1));
}

__device__ __forceinline__ uint32_t f32_to_tf32(float x) {
    uint32_t r;
    asm("cvt.rna.tf32.f32 %0, %1;" : "=r"(r) : "f"(x));
    return r;
}

// ===========================================================================
// tf32 tensor-core NT-GEMM with fused bias + head-split scatter.
//   A: [16384, 1024] fp32 row-major;  W: [1024, 1024] fp32 row-major (K-major)
//   out[B,H,S,Dh] = A @ W^T + bias
// CTA tile 128x128, BK=32 double-buffered smem (stride-36 pad, conflict-free
// fragment reads). 8 warps in 2(M)x4(N) grid of 64x32 warp tiles.
// Fragments per PTX m16n8k8 .row.col mapping: g=lane>>2, t=lane&3.
// ===========================================================================
constexpr int GSTRIDE = 36;                    // smem row stride in floats
constexpr int TILE_F  = 128 * GSTRIDE;         // 4608 floats per tile
constexpr int GEMM_SMEM_BYTES = 4 * TILE_F * 4;  // 2 stages x (A+W) = 73728 B

__global__ __launch_bounds__(256) void qkv_gemm_mma(
    const float* __restrict__ A,
    const float* __restrict__ W,
    const float* __restrict__ bias,
    float* __restrict__ out)
{
    extern __shared__ float smf[];
    // layout: [A0][W0][A1][W1], each TILE_F floats
    const int tid  = threadIdx.x;
    const int lane = tid & 31;
    const int wid  = tid >> 5;
    const int wm   = wid >> 2;   // 0..1
    const int wn   = wid & 3;    // 0..3
    const int g    = lane >> 2;  // 0..7
    const int t    = lane & 3;   // 0..3

    const int m0 = blockIdx.y * 128;
    const int n0 = blockIdx.x * 128;

    const float* Ap = A + (size_t)m0 * 1024;
    const float* Wp = W + (size_t)n0 * 1024;

    // global load mapping: 4 iters, gi = tid + it*256; row = gi>>3, kg = gi&7
    const int lrow0 = tid >> 3;        // +32 per iter
    const int lkg   = (tid & 7) * 4;

    float acc[4][4][4];
#pragma unroll
    for (int i = 0; i < 4; i++)
#pragma unroll
        for (int j = 0; j < 4; j++)
#pragma unroll
            for (int r = 0; r < 4; r++) acc[i][j][r] = 0.f;

    // ---- prologue: stage 0 -> buffer 0 ----
    {
        float* As = smf;
        float* Ws = smf + TILE_F;
#pragma unroll
        for (int it = 0; it < 4; it++) {
            const int row = lrow0 + it * 32;
            const float4 av = *reinterpret_cast<const float4*>(Ap + (size_t)row * 1024 + lkg);
            const float4 wv = *reinterpret_cast<const float4*>(Wp + (size_t)row * 1024 + lkg);
            uint4 ac = make_uint4(f32_to_tf32(av.x), f32_to_tf32(av.y),
                                  f32_to_tf32(av.z), f32_to_tf32(av.w));
            uint4 wc = make_uint4(f32_to_tf32(wv.x), f32_to_tf32(wv.y),
                                  f32_to_tf32(wv.z), f32_to_tf32(wv.w));
            *reinterpret_cast<uint4*>(As + row * GSTRIDE + lkg) = ac;
            *reinterpret_cast<uint4*>(Ws + row * GSTRIDE + lkg) = wc;
        }
    }
    __syncthreads();

    constexpr int NS = 1024 / 32;   // 32 stages
    for (int s = 0; s < NS; s++) {
        const int buf = s & 1;
        const float* As = smf + buf * 2 * TILE_F;
        const float* Ws = As + TILE_F;

        // prefetch next stage into registers
        float4 pa[4], pw[4];
        if (s + 1 < NS) {
            const int k0 = (s + 1) * 32;
#pragma unroll
            for (int it = 0; it < 4; it++) {
                const int row = lrow0 + it * 32;
                pa[it] = *reinterpret_cast<const float4*>(Ap + (size_t)row * 1024 + k0 + lkg);
                pw[it] = *reinterpret_cast<const float4*>(Wp + (size_t)row * 1024 + k0 + lkg);
            }
        }

        // compute: 4 k8-steps over this BK=32 stage
        const uint32_t* Asu = reinterpret_cast<const uint32_t*>(As);
        const uint32_t* Wsu = reinterpret_cast<const uint32_t*>(Ws);
#pragma unroll
        for (int k8 = 0; k8 < 4; k8++) {
            const int kk = k8 * 8;
            uint32_t af[4][4];
#pragma unroll
            for (int mb = 0; mb < 4; mb++) {
                const int r = wm * 64 + mb * 16 + g;
                af[mb][0] = Asu[r * GSTRIDE + kk + t];
                af[mb][1] = Asu[(r + 8) * GSTRIDE + kk + t];
                af[mb][2] = Asu[r * GSTRIDE + kk + t + 4];
                af[mb][3] = Asu[(r + 8) * GSTRIDE + kk + t + 4];
            }
            uint32_t bf[4][2];
#pragma unroll
            for (int nb = 0; nb < 4; nb++) {
                const int n = wn * 32 + nb * 8 + g;
                bf[nb][0] = Wsu[n * GSTRIDE + kk + t];
                bf[nb][1] = Wsu[n * GSTRIDE + kk + t + 4];
            }
#pragma unroll
            for (int mb = 0; mb < 4; mb++)
#pragma unroll
                for (int nb = 0; nb < 4; nb++)
                    mma_tf32_16x8x8(acc[mb][nb][0], acc[mb][nb][1],
                                    acc[mb][nb][2], acc[mb][nb][3],
                                    af[mb][0], af[mb][1], af[mb][2], af[mb][3],
                                    bf[nb][0], bf[nb][1]);
        }

        // store next stage into the other buffer
        if (s + 1 < NS) {
            float* An = smf + (buf ^ 1) * 2 * TILE_F;
            float* Wn = An + TILE_F;
#pragma unroll
            for (int it = 0; it < 4; it++) {
                const int row = lrow0 + it * 32;
                uint4 ac = make_uint4(f32_to_tf32(pa[it].x), f32_to_tf32(pa[it].y),
                                      f32_to_tf32(pa[it].z), f32_to_tf32(pa[it].w));
                uint4 wc = make_uint4(f32_to_tf32(pw[it].x), f32_to_tf32(pw[it].y),
                                      f32_to_tf32(pw[it].z), f32_to_tf32(pw[it].w));
                *reinterpret_cast<uint4*>(An + row * GSTRIDE + lkg) = ac;
                *reinterpret_cast<uint4*>(Wn + row * GSTRIDE + lkg) = wc;
            }
            __syncthreads();
        }
    }

    // ---- epilogue: + bias, scatter to out[B,H,S,Dh] ----
#pragma unroll
    for (int mb = 0; mb < 4; mb++) {
        const int m_lo = m0 + wm * 64 + mb * 16 + g;
#pragma unroll
        for (int nb = 0; nb < 4; nb++) {
            const int n  = n0 + wn * 32 + nb * 8 + 2 * t;
            const int h  = n >> 6;
            const int dh = n & 63;
            const float b0 = __ldg(&bias[n + 0]);
            const float b1 = __ldg(&bias[n + 1]);
            {
                const int bb = m_lo >> 10;
                const int ss = m_lo & 1023;
                float2 o = make_float2(acc[mb][nb][0] + b0, acc[mb][nb][1] + b1);
                *reinterpret_cast<float2*>(
                    out + (((size_t)(bb * 16 + h)) << 16) + ((size_t)ss << 6) + dh) = o;
            }
            {
                const int m_hi = m_lo + 8;
                const int bb = m_hi >> 10;
                const int ss = m_hi & 1023;
                float2 o = make_float2(acc[mb][nb][2] + b0, acc[mb][nb][3] + b1);
                *reinterpret_cast<float2*>(
                    out + (((size_t)(bb * 16 + h)) << 16) + ((size_t)ss << 6) + dh) = o;
            }
        }
    }
}

// ---------------------------------------------------------------------------
// Flash attention, register-blocked 8x8 per thread (unchanged from R2).
// ---------------------------------------------------------------------------
__global__ __launch_bounds__(128) void attn_kernel(
    const float* __restrict__ Qg,
    const float* __restrict__ Kg,
    const float* __restrict__ Vg,
    float* __restrict__ out)
{
    extern __shared__ float sm[];
    float* Qs = sm;                  // 64*128
    float* Ks = sm + 64 * 128;       // 64*64
    float* Vs = Ks + 64 * 64;        // 64*64
    float* Ps = Vs + 64 * 64;        // 64*128

    const int tid  = threadIdx.x;
    const int tRow = tid >> 3;   // 0..15
    const int tCol = tid & 7;    // 0..7

    const int bh = blockIdx.y;
    const int q0 = blockIdx.x * 128;

    const float* Qp = Qg + ((size_t)bh << 16) + (size_t)q0 * 64;
    const float* Kp = Kg + ((size_t)bh << 16);
    const float* Vp = Vg + ((size_t)bh << 16);

    {
        const int rl = tid >> 4;
        const int gq = tid & 15;
#pragma unroll
        for (int rep = 0; rep < 16; rep++) {
            const int r = rl + rep * 8;
            float4 v = *reinterpret_cast<const float4*>(Qp + (size_t)r * 64 + gq * 4);
            const int sw = ((((r >> 2) ^ gq) & 31) << 2) + (r & 3);
            Qs[(4 * gq + 0) * 128 + sw] = v.x;
            Qs[(4 * gq + 1) * 128 + sw] = v.y;
            Qs[(4 * gq + 2) * 128 + sw] = v.z;
            Qs[(4 * gq + 3) * 128 + sw] = v.w;
        }
    }

    float m_[8], l_[8];
    float O[8][8];
#pragma unroll
    for (int i = 0; i < 8; i++) {
        m_[i] = -1e30f;
        l_[i] = 0.f;
#pragma unroll
        for (int j = 0; j < 8; j++) O[i][j] = 0.f;
    }

    for (int t = 0; t < Sn / 64; t++) {
        __syncthreads();

        {
            const int cl = tid >> 4;
            const int gk = tid & 15;
#pragma unroll
            for (int rep = 0; rep < 8; rep++) {
                const int c = cl + rep * 8;
                const float4 kv = *reinterpret_cast<const float4*>(
                    Kp + (size_t)(t * 64 + c) * 64 + gk * 4);
                const int sw = ((((c >> 2) ^ gk) & 15) << 2) + (c & 3);
                Ks[(4 * gk + 0) * 64 + sw] = kv.x;
                Ks[(4 * gk + 1) * 64 + sw] = kv.y;
                Ks[(4 * gk + 2) * 64 + sw] = kv.z;
                Ks[(4 * gk + 3) * 64 + sw] = kv.w;
                const float4 vv = *reinterpret_cast<const float4*>(
                    Vp + (size_t)(t * 64 + c) * 64 + gk * 4);
                *reinterpret_cast<float4*>(Vs + c * 64 + gk * 4) = vv;
            }
        }
        __syncthreads();

        float s[8][8];
#pragma unroll
        for (int i = 0; i < 8; i++)
#pragma unroll
            for (int j = 0; j < 8; j++) s[i][j] = 0.f;

        for (int k4 = 0; k4 < 16; k4++) {
            const float* qb = Qs + k4 * 4 * 128;
            const float* kb = Ks + k4 * 4 * 64;
            const int gq0 = (((2 * tRow) ^ k4) & 31) << 2;
            const int gq1 = (((2 * tRow + 1) ^ k4) & 31) << 2;
            const int gk0 = ((tCol ^ k4) & 15) << 2;
            const int gk1 = (((tCol + 8) ^ k4) & 15) << 2;
#pragma unroll
            for (int kk = 0; kk < 4; kk++) {
                const float4 a0 = *reinterpret_cast<const float4*>(qb + kk * 128 + gq0);
                const float4 a1 = *reinterpret_cast<const float4*>(qb + kk * 128 + gq1);
                const float4 b0 = *reinterpret_cast<const float4*>(kb + kk * 64 + gk0);
                const float4 b1 = *reinterpret_cast<const float4*>(kb + kk * 64 + gk1);
                const float am[8] = {a0.x, a0.y, a0.z, a0.w, a1.x, a1.y, a1.z, a1.w};
                const float bn[8] = {b0.x, b0.y, b0.z, b0.w, b1.x, b1.y, b1.z, b1.w};
#pragma unroll
                for (int i = 0; i < 8; i++)
#pragma unroll
                    for (int j = 0; j < 8; j++)
                        s[i][j] = fmaf(am[i], bn[j], s[i][j]);
            }
        }

        constexpr float scale = 0.125f;
#pragma unroll
        for (int i = 0; i < 8; i++) {
            float mt = -1e30f;
#pragma unroll
            for (int j = 0; j < 8; j++) {
                s[i][j] *= scale;
                mt = fmaxf(mt, s[i][j]);
            }
            mt = fmaxf(mt, __shfl_xor_sync(0xffffffffu, mt, 1));
            mt = fmaxf(mt, __shfl_xor_sync(0xffffffffu, mt, 2));
            mt = fmaxf(mt, __shfl_xor_sync(0xffffffffu, mt, 4));

            const float mn    = fmaxf(m_[i], mt);
            const float alpha = __expf(m_[i] - mn);
            float ls = 0.f;
#pragma unroll
            for (int j = 0; j < 8; j++) {
                s[i][j] = __expf(s[i][j] - mn);
                ls += s[i][j];
            }
            ls += __shfl_xor_sync(0xffffffffu, ls, 1);
            ls += __shfl_xor_sync(0xffffffffu, ls, 2);
            ls += __shfl_xor_sync(0xffffffffu, ls, 4);
            l_[i] = alpha * l_[i] + ls;
            m_[i] = mn;
#pragma unroll
            for (int j = 0; j < 8; j++) O[i][j] *= alpha;
        }

#pragma unroll
        for (int jj = 0; jj < 8; jj++) {
            const int c  = (jj < 4) ? (tCol * 4 + jj) : (32 + tCol * 4 + (jj - 4));
            const int f3 = c >> 2;
            const float4 p0 = make_float4(s[0][jj], s[1][jj], s[2][jj], s[3][jj]);
            const float4 p1 = make_float4(s[4][jj], s[5][jj], s[6][jj], s[7][jj]);
            *reinterpret_cast<float4*>(
                Ps + c * 128 + ((((2 * tRow) ^ f3) & 31) << 2)) = p0;
            *reinterpret_cast<float4*>(
                Ps + c * 128 + ((((2 * tRow + 1) ^ f3) & 31) << 2)) = p1;
        }
        __syncthreads();

        for (int c4 = 0; c4 < 16; c4++) {
            const float* pb = Ps + c4 * 4 * 128;
            const float* vb = Vs + c4 * 4 * 64;
            const int gp0 = (((2 * tRow) ^ c4) & 31) << 2;
            const int gp1 = (((2 * tRow + 1) ^ c4) & 31) << 2;
#pragma unroll
            for (int cc = 0; cc < 4; cc++) {
                const float4 p0 = *reinterpret_cast<const float4*>(pb + cc * 128 + gp0);
                const float4 p1 = *reinterpret_cast<const float4*>(pb + cc * 128 + gp1);
                const float4 v0 = *reinterpret_cast<const float4*>(vb + cc * 64 + tCol * 4);
                const float4 v1 = *reinterpret_cast<const float4*>(vb + cc * 64 + 32 + tCol * 4);
                const float pm[8] = {p0.x, p0.y, p0.z, p0.w, p1.x, p1.y, p1.z, p1.w};
                const float vn[8] = {v0.x, v0.y, v0.z, v0.w, v1.x, v1.y, v1.z, v1.w};
#pragma unroll
                for (int i = 0; i < 8; i++)
#pragma unroll
                    for (int j = 0; j < 8; j++)
                        O[i][j] = fmaf(pm[i], vn[j], O[i][j]);
            }
        }
    }

    const int b = bh >> 4;
    const int h = bh & 15;
#pragma unroll
    for (int i = 0; i < 8; i++) {
        const float inv = 1.0f / l_[i];
        const int row = q0 + tRow * 8 + i;
        float* op = out + (size_t)(b * Sn + row) * Dn + h * DhN;
        float4 o0, o1;
        o0.x = O[i][0] * inv; o0.y = O[i][1] * inv;
        o0.z = O[i][2] * inv; o0.w = O[i][3] * inv;
        o1.x = O[i][4] * inv; o1.y = O[i][5] * inv;
        o1.z = O[i][6] * inv; o1.w = O[i][7] * inv;
        *reinterpret_cast<float4*>(op + tCol * 4) = o0;
        *reinterpret_cast<float4*>(op + 32 + tCol * 4) = o1;
    }
}

// ---------------------------------------------------------------------------
extern "C" void kernel_launch(void* const* d_in, const int* in_sizes, int n_in,
                              void* d_out, int out_size)
{
    const float* X  = (const float*)d_in[0];
    const float* Wq = (const float*)d_in[1];
    const float* bq = (const float*)d_in[2];
    const float* Wk = (const float*)d_in[3];
    const float* bk = (const float*)d_in[4];
    const float* Wv = (const float*)d_in[5];
    const float* bv = (const float*)d_in[6];
    float* out = (float*)d_out;

    float *q, *k, *v;
    cudaGetSymbolAddress((void**)&q, g_q);
    cudaGetSymbolAddress((void**)&k, g_k);
    cudaGetSymbolAddress((void**)&v, g_v);

    cudaFuncSetAttribute(qkv_gemm_mma,
                         cudaFuncAttributeMaxDynamicSharedMemorySize, GEMM_SMEM_BYTES);
    const dim3 gemm_grid(Dn / 128, (Bn * Sn) / 128);  // (8, 128)
    qkv_gemm_mma<<<gemm_grid, 256, GEMM_SMEM_BYTES>>>(X, Wq, bq, q);
    qkv_gemm_mma<<<gemm_grid, 256, GEMM_SMEM_BYTES>>>(X, Wk, bk, k);
    qkv_gemm_mma<<<gemm_grid, 256, GEMM_SMEM_BYTES>>>(X, Wv, bv, v);

    const int attn_smem = 96 * 1024;
    cudaFuncSetAttribute(attn_kernel,
                         cudaFuncAttributeMaxDynamicSharedMemorySize, attn_smem);
    const dim3 attn_grid(Sn / 128, Bn * Hn);          // (8, 256)
    attn_kernel<<<attn_grid, 128, attn_smem>>>(q, k, v, out);
}

// round 5
// speedup vs baseline: 7.1518x; 1.8328x over previous
#include <cuda_runtime.h>
#include <math.h>
#include <cstdint>

// Problem constants: B=16, S=1024, D=1024, H=16, Dh=64
constexpr int Bn = 16;
constexpr int Sn = 1024;
constexpr int Dn = 1024;
constexpr int Hn = 16;
constexpr int DhN = 64;

// Scratch Q/K/V in [B,H,S,Dh] layout (device globals: allowed scratch)
__device__ float g_q[(size_t)Bn * Hn * Sn * DhN];
__device__ float g_k[(size_t)Bn * Hn * Sn * DhN];
__device__ float g_v[(size_t)Bn * Hn * Sn * DhN];

// ===========================================================================
// mma.sync tf32 helpers (arch-independent PTX, works on plain compute_103)
// ===========================================================================
__device__ __forceinline__ void mma_tf32_16x8x8(
    float& d0, float& d1, float& d2, float& d3,
    uint32_t a0, uint32_t a1, uint32_t a2, uint32_t a3,
    uint32_t b0, uint32_t b1)
{
    asm volatile(
        "mma.sync.aligned.m16n8k8.row.col.f32.tf32.tf32.f32 "
        "{%0,%1,%2,%3}, {%4,%5,%6,%7}, {%8,%9}, {%0,%1,%2,%3};"
        : "+f"(d0), "+f"(d1), "+f"(d2), "+f"(d3)
        : "r"(a0), "r"(a1), "r"(a2), "r"(a3), "r"(b0), "r"(b1));
}

__device__ __forceinline__ uint32_t f32_to_tf32(float x) {
    uint32_t r;
    asm("cvt.rna.tf32.f32 %0, %1;" : "=r"(r) : "f"(x));
    return r;
}

// ===========================================================================
// tf32 tensor-core NT-GEMM with fused bias + head-split scatter (R4).
// ===========================================================================
constexpr int GSTRIDE = 36;                    // smem row stride in floats
constexpr int TILE_F  = 128 * GSTRIDE;         // 4608 floats per tile
constexpr int GEMM_SMEM_BYTES = 4 * TILE_F * 4;  // 73728 B

__global__ __launch_bounds__(256) void qkv_gemm_mma(
    const float* __restrict__ A,
    const float* __restrict__ W,
    const float* __restrict__ bias,
    float* __restrict__ out)
{
    extern __shared__ float smf[];
    const int tid  = threadIdx.x;
    const int lane = tid & 31;
    const int wid  = tid >> 5;
    const int wm   = wid >> 2;
    const int wn   = wid & 3;
    const int g    = lane >> 2;
    const int t    = lane & 3;

    const int m0 = blockIdx.y * 128;
    const int n0 = blockIdx.x * 128;

    const float* Ap = A + (size_t)m0 * 1024;
    const float* Wp = W + (size_t)n0 * 1024;

    const int lrow0 = tid >> 3;
    const int lkg   = (tid & 7) * 4;

    float acc[4][4][4];
#pragma unroll
    for (int i = 0; i < 4; i++)
#pragma unroll
        for (int j = 0; j < 4; j++)
#pragma unroll
            for (int r = 0; r < 4; r++) acc[i][j][r] = 0.f;

    {
        float* As = smf;
        float* Ws = smf + TILE_F;
#pragma unroll
        for (int it = 0; it < 4; it++) {
            const int row = lrow0 + it * 32;
            const float4 av = *reinterpret_cast<const float4*>(Ap + (size_t)row * 1024 + lkg);
            const float4 wv = *reinterpret_cast<const float4*>(Wp + (size_t)row * 1024 + lkg);
            uint4 ac = make_uint4(f32_to_tf32(av.x), f32_to_tf32(av.y),
                                  f32_to_tf32(av.z), f32_to_tf32(av.w));
            uint4 wc = make_uint4(f32_to_tf32(wv.x), f32_to_tf32(wv.y),
                                  f32_to_tf32(wv.z), f32_to_tf32(wv.w));
            *reinterpret_cast<uint4*>(As + row * GSTRIDE + lkg) = ac;
            *reinterpret_cast<uint4*>(Ws + row * GSTRIDE + lkg) = wc;
        }
    }
    __syncthreads();

    constexpr int NS = 1024 / 32;
    for (int s = 0; s < NS; s++) {
        const int buf = s & 1;
        const float* As = smf + buf * 2 * TILE_F;
        const float* Ws = As + TILE_F;

        float4 pa[4], pw[4];
        if (s + 1 < NS) {
            const int k0 = (s + 1) * 32;
#pragma unroll
            for (int it = 0; it < 4; it++) {
                const int row = lrow0 + it * 32;
                pa[it] = *reinterpret_cast<const float4*>(Ap + (size_t)row * 1024 + k0 + lkg);
                pw[it] = *reinterpret_cast<const float4*>(Wp + (size_t)row * 1024 + k0 + lkg);
            }
        }

        const uint32_t* Asu = reinterpret_cast<const uint32_t*>(As);
        const uint32_t* Wsu = reinterpret_cast<const uint32_t*>(Ws);
#pragma unroll
        for (int k8 = 0; k8 < 4; k8++) {
            const int kk = k8 * 8;
            uint32_t af[4][4];
#pragma unroll
            for (int mb = 0; mb < 4; mb++) {
                const int r = wm * 64 + mb * 16 + g;
                af[mb][0] = Asu[r * GSTRIDE + kk + t];
                af[mb][1] = Asu[(r + 8) * GSTRIDE + kk + t];
                af[mb][2] = Asu[r * GSTRIDE + kk + t + 4];
                af[mb][3] = Asu[(r + 8) * GSTRIDE + kk + t + 4];
            }
            uint32_t bf[4][2];
#pragma unroll
            for (int nb = 0; nb < 4; nb++) {
                const int n = wn * 32 + nb * 8 + g;
                bf[nb][0] = Wsu[n * GSTRIDE + kk + t];
                bf[nb][1] = Wsu[n * GSTRIDE + kk + t + 4];
            }
#pragma unroll
            for (int mb = 0; mb < 4; mb++)
#pragma unroll
                for (int nb = 0; nb < 4; nb++)
                    mma_tf32_16x8x8(acc[mb][nb][0], acc[mb][nb][1],
                                    acc[mb][nb][2], acc[mb][nb][3],
                                    af[mb][0], af[mb][1], af[mb][2], af[mb][3],
                                    bf[nb][0], bf[nb][1]);
        }

        if (s + 1 < NS) {
            float* An = smf + (buf ^ 1) * 2 * TILE_F;
            float* Wn = An + TILE_F;
#pragma unroll
            for (int it = 0; it < 4; it++) {
                const int row = lrow0 + it * 32;
                uint4 ac = make_uint4(f32_to_tf32(pa[it].x), f32_to_tf32(pa[it].y),
                                      f32_to_tf32(pa[it].z), f32_to_tf32(pa[it].w));
                uint4 wc = make_uint4(f32_to_tf32(pw[it].x), f32_to_tf32(pw[it].y),
                                      f32_to_tf32(pw[it].z), f32_to_tf32(pw[it].w));
                *reinterpret_cast<uint4*>(An + row * GSTRIDE + lkg) = ac;
                *reinterpret_cast<uint4*>(Wn + row * GSTRIDE + lkg) = wc;
            }
            __syncthreads();
        }
    }

#pragma unroll
    for (int mb = 0; mb < 4; mb++) {
        const int m_lo = m0 + wm * 64 + mb * 16 + g;
#pragma unroll
        for (int nb = 0; nb < 4; nb++) {
            const int n  = n0 + wn * 32 + nb * 8 + 2 * t;
            const int h  = n >> 6;
            const int dh = n & 63;
            const float b0 = __ldg(&bias[n + 0]);
            const float b1 = __ldg(&bias[n + 1]);
            {
                const int bb = m_lo >> 10;
                const int ss = m_lo & 1023;
                float2 o = make_float2(acc[mb][nb][0] + b0, acc[mb][nb][1] + b1);
                *reinterpret_cast<float2*>(
                    out + (((size_t)(bb * 16 + h)) << 16) + ((size_t)ss << 6) + dh) = o;
            }
            {
                const int m_hi = m_lo + 8;
                const int bb = m_hi >> 10;
                const int ss = m_hi & 1023;
                float2 o = make_float2(acc[mb][nb][2] + b0, acc[mb][nb][3] + b1);
                *reinterpret_cast<float2*>(
                    out + (((size_t)(bb * 16 + h)) << 16) + ((size_t)ss << 6) + dh) = o;
            }
        }
    }
}

// ===========================================================================
// tf32 tensor-core flash attention.
//   CTA: 128 query rows, 4 warps x 32 rows (2 m16 tiles). BC=64 keys/iter.
//   Q fragments in registers (staged once through Ps).
//   smem: Ks[key][d] stride 68 (tf32), Vs[dh][key] stride 69 (tf32, transposed),
//         Ps[q][key] stride 68 (tf32 P round-trip; warp-private rows).
// ===========================================================================
constexpr int KSTR = 68;
constexpr int VSTR = 69;
constexpr int KS_F = 64 * KSTR;            // 4352
constexpr int VS_F = 64 * VSTR;            // 4416
constexpr int PS_F = 128 * KSTR;           // 8704
constexpr int ATTN_SMEM_BYTES = (KS_F + VS_F + PS_F) * 4;  // 69888

__global__ __launch_bounds__(128) void attn_mma(
    const float* __restrict__ Qg,
    const float* __restrict__ Kg,
    const float* __restrict__ Vg,
    float* __restrict__ out)
{
    extern __shared__ float sm[];
    uint32_t* Ksu = reinterpret_cast<uint32_t*>(sm);
    uint32_t* Vsu = Ksu + KS_F;
    uint32_t* Psu = Vsu + VS_F;

    const int tid  = threadIdx.x;
    const int lane = tid & 31;
    const int wid  = tid >> 5;     // 0..3
    const int g    = lane >> 2;    // 0..7
    const int t    = lane & 3;     // 0..3

    const int bh = blockIdx.y;     // b*16 + h
    const int q0 = blockIdx.x * 128;

    const float* Qp = Qg + ((size_t)bh << 16) + (size_t)q0 * 64;
    const float* Kp = Kg + ((size_t)bh << 16);
    const float* Vp = Vg + ((size_t)bh << 16);

    // ---- Stage Q through Ps, then pull A-fragments into registers ----
    {
#pragma unroll
        for (int rep = 0; rep < 16; rep++) {
            const int idx = tid + rep * 128;        // 0..2047
            const int row = idx >> 4;               // 0..127
            const int g4  = (idx & 15) * 4;
            const float4 v = *reinterpret_cast<const float4*>(Qp + (size_t)row * 64 + g4);
            uint4 c = make_uint4(f32_to_tf32(v.x), f32_to_tf32(v.y),
                                 f32_to_tf32(v.z), f32_to_tf32(v.w));
            *reinterpret_cast<uint4*>(Psu + row * KSTR + g4) = c;
        }
    }
    __syncthreads();

    uint32_t qf[2][8][4];
#pragma unroll
    for (int mt = 0; mt < 2; mt++) {
        const int r0 = wid * 32 + mt * 16 + g;
#pragma unroll
        for (int ks = 0; ks < 8; ks++) {
            const int kk = ks * 8;
            qf[mt][ks][0] = Psu[r0 * KSTR + kk + t];
            qf[mt][ks][1] = Psu[(r0 + 8) * KSTR + kk + t];
            qf[mt][ks][2] = Psu[r0 * KSTR + kk + t + 4];
            qf[mt][ks][3] = Psu[(r0 + 8) * KSTR + kk + t + 4];
        }
    }

    float m_[2][2], l_[2][2];
    float oacc[2][8][4];
#pragma unroll
    for (int mt = 0; mt < 2; mt++) {
        m_[mt][0] = -1e30f; m_[mt][1] = -1e30f;
        l_[mt][0] = 0.f;    l_[mt][1] = 0.f;
#pragma unroll
        for (int n = 0; n < 8; n++)
#pragma unroll
            for (int j = 0; j < 4; j++) oacc[mt][n][j] = 0.f;
    }

    for (int it = 0; it < Sn / 64; it++) {
        __syncthreads();   // all warps done with previous Ks/Vs (and Q-frag reads)

        // ---- Load K tile (tf32, [key][d] stride 68) and V tile transposed ----
#pragma unroll
        for (int rep = 0; rep < 8; rep++) {
            const int idx = tid + rep * 128;     // 0..1023
            const int c   = idx >> 4;            // key 0..63
            const int g4  = (idx & 15) * 4;      // d group
            const float4 kv = *reinterpret_cast<const float4*>(
                Kp + (size_t)(it * 64 + c) * 64 + g4);
            uint4 kc = make_uint4(f32_to_tf32(kv.x), f32_to_tf32(kv.y),
                                  f32_to_tf32(kv.z), f32_to_tf32(kv.w));
            *reinterpret_cast<uint4*>(Ksu + c * KSTR + g4) = kc;
            const float4 vv = *reinterpret_cast<const float4*>(
                Vp + (size_t)(it * 64 + c) * 64 + g4);
            Vsu[(g4 + 0) * VSTR + c] = f32_to_tf32(vv.x);
            Vsu[(g4 + 1) * VSTR + c] = f32_to_tf32(vv.y);
            Vsu[(g4 + 2) * VSTR + c] = f32_to_tf32(vv.z);
            Vsu[(g4 + 3) * VSTR + c] = f32_to_tf32(vv.w);
        }
        __syncthreads();

        // ---- Score GEMM: sacc[2][8][4] = Q . K^T ----
        float sacc[2][8][4];
#pragma unroll
        for (int mt = 0; mt < 2; mt++)
#pragma unroll
            for (int n = 0; n < 8; n++)
#pragma unroll
                for (int j = 0; j < 4; j++) sacc[mt][n][j] = 0.f;

#pragma unroll
        for (int ks = 0; ks < 8; ks++) {
            const int kk = ks * 8;
            uint32_t bf[8][2];
#pragma unroll
            for (int n = 0; n < 8; n++) {
                bf[n][0] = Ksu[(8 * n + g) * KSTR + kk + t];
                bf[n][1] = Ksu[(8 * n + g) * KSTR + kk + t + 4];
            }
#pragma unroll
            for (int mt = 0; mt < 2; mt++)
#pragma unroll
                for (int n = 0; n < 8; n++)
                    mma_tf32_16x8x8(sacc[mt][n][0], sacc[mt][n][1],
                                    sacc[mt][n][2], sacc[mt][n][3],
                                    qf[mt][ks][0], qf[mt][ks][1],
                                    qf[mt][ks][2], qf[mt][ks][3],
                                    bf[n][0], bf[n][1]);
        }

        // ---- Online softmax on C-fragment layout ----
        constexpr float scale = 0.125f;   // 1/sqrt(64)
#pragma unroll
        for (int mt = 0; mt < 2; mt++) {
            float mx0 = -1e30f, mx1 = -1e30f;
#pragma unroll
            for (int n = 0; n < 8; n++) {
                sacc[mt][n][0] *= scale; sacc[mt][n][1] *= scale;
                sacc[mt][n][2] *= scale; sacc[mt][n][3] *= scale;
                mx0 = fmaxf(mx0, fmaxf(sacc[mt][n][0], sacc[mt][n][1]));
                mx1 = fmaxf(mx1, fmaxf(sacc[mt][n][2], sacc[mt][n][3]));
            }
            mx0 = fmaxf(mx0, __shfl_xor_sync(0xffffffffu, mx0, 1));
            mx0 = fmaxf(mx0, __shfl_xor_sync(0xffffffffu, mx0, 2));
            mx1 = fmaxf(mx1, __shfl_xor_sync(0xffffffffu, mx1, 1));
            mx1 = fmaxf(mx1, __shfl_xor_sync(0xffffffffu, mx1, 2));

            const float mn0 = fmaxf(m_[mt][0], mx0);
            const float mn1 = fmaxf(m_[mt][1], mx1);
            const float a0  = __expf(m_[mt][0] - mn0);
            const float a1  = __expf(m_[mt][1] - mn1);
            float ls0 = 0.f, ls1 = 0.f;
#pragma unroll
            for (int n = 0; n < 8; n++) {
                sacc[mt][n][0] = __expf(sacc[mt][n][0] - mn0);
                sacc[mt][n][1] = __expf(sacc[mt][n][1] - mn0);
                sacc[mt][n][2] = __expf(sacc[mt][n][2] - mn1);
                sacc[mt][n][3] = __expf(sacc[mt][n][3] - mn1);
                ls0 += sacc[mt][n][0] + sacc[mt][n][1];
                ls1 += sacc[mt][n][2] + sacc[mt][n][3];
            }
            ls0 += __shfl_xor_sync(0xffffffffu, ls0, 1);
            ls0 += __shfl_xor_sync(0xffffffffu, ls0, 2);
            ls1 += __shfl_xor_sync(0xffffffffu, ls1, 1);
            ls1 += __shfl_xor_sync(0xffffffffu, ls1, 2);
            l_[mt][0] = a0 * l_[mt][0] + ls0;
            l_[mt][1] = a1 * l_[mt][1] + ls1;
            m_[mt][0] = mn0;
            m_[mt][1] = mn1;
#pragma unroll
            for (int n = 0; n < 8; n++) {
                oacc[mt][n][0] *= a0; oacc[mt][n][1] *= a0;
                oacc[mt][n][2] *= a1; oacc[mt][n][3] *= a1;
            }

            // Write P (tf32) to warp-private rows of Ps
            const int r0 = wid * 32 + mt * 16 + g;
#pragma unroll
            for (int n = 0; n < 8; n++) {
                const int col = 8 * n + 2 * t;
                uint2 p0 = make_uint2(f32_to_tf32(sacc[mt][n][0]),
                                      f32_to_tf32(sacc[mt][n][1]));
                uint2 p1 = make_uint2(f32_to_tf32(sacc[mt][n][2]),
                                      f32_to_tf32(sacc[mt][n][3]));
                *reinterpret_cast<uint2*>(Psu + r0 * KSTR + col) = p0;
                *reinterpret_cast<uint2*>(Psu + (r0 + 8) * KSTR + col) = p1;
            }
        }
        __syncwarp();   // order P stores vs cross-lane fragment loads (same warp rows)

        // ---- PV GEMM: oacc += P . V ----
#pragma unroll
        for (int ks = 0; ks < 8; ks++) {
            const int kk = ks * 8;
            uint32_t pf[2][4];
#pragma unroll
            for (int mt = 0; mt < 2; mt++) {
                const int r0 = wid * 32 + mt * 16 + g;
                pf[mt][0] = Psu[r0 * KSTR + kk + t];
                pf[mt][1] = Psu[(r0 + 8) * KSTR + kk + t];
                pf[mt][2] = Psu[r0 * KSTR + kk + t + 4];
                pf[mt][3] = Psu[(r0 + 8) * KSTR + kk + t + 4];
            }
            uint32_t vf[8][2];
#pragma unroll
            for (int n = 0; n < 8; n++) {
                vf[n][0] = Vsu[(8 * n + g) * VSTR + kk + t];
                vf[n][1] = Vsu[(8 * n + g) * VSTR + kk + t + 4];
            }
#pragma unroll
            for (int mt = 0; mt < 2; mt++)
#pragma unroll
                for (int n = 0; n < 8; n++)
                    mma_tf32_16x8x8(oacc[mt][n][0], oacc[mt][n][1],
                                    oacc[mt][n][2], oacc[mt][n][3],
                                    pf[mt][0], pf[mt][1], pf[mt][2], pf[mt][3],
                                    vf[n][0], vf[n][1]);
        }
    }

    // ---- Epilogue: normalize, write out[B,S,H*Dh] ----
    const int b = bh >> 4;
    const int h = bh & 15;
#pragma unroll
    for (int mt = 0; mt < 2; mt++) {
        const float inv0 = 1.0f / l_[mt][0];
        const float inv1 = 1.0f / l_[mt][1];
        const int r0 = q0 + wid * 32 + mt * 16 + g;
#pragma unroll
        for (int n = 0; n < 8; n++) {
            const int col = h * 64 + 8 * n + 2 * t;
            float2 o0 = make_float2(oacc[mt][n][0] * inv0, oacc[mt][n][1] * inv0);
            float2 o1 = make_float2(oacc[mt][n][2] * inv1, oacc[mt][n][3] * inv1);
            *reinterpret_cast<float2*>(out + (size_t)(b * Sn + r0) * Dn + col) = o0;
            *reinterpret_cast<float2*>(out + (size_t)(b * Sn + r0 + 8) * Dn + col) = o1;
        }
    }
}

// ---------------------------------------------------------------------------
extern "C" void kernel_launch(void* const* d_in, const int* in_sizes, int n_in,
                              void* d_out, int out_size)
{
    const float* X  = (const float*)d_in[0];
    const float* Wq = (const float*)d_in[1];
    const float* bq = (const float*)d_in[2];
    const float* Wk = (const float*)d_in[3];
    const float* bk = (const float*)d_in[4];
    const float* Wv = (const float*)d_in[5];
    const float* bv = (const float*)d_in[6];
    float* out = (float*)d_out;

    float *q, *k, *v;
    cudaGetSymbolAddress((void**)&q, g_q);
    cudaGetSymbolAddress((void**)&k, g_k);
    cudaGetSymbolAddress((void**)&v, g_v);

    cudaFuncSetAttribute(qkv_gemm_mma,
                         cudaFuncAttributeMaxDynamicSharedMemorySize, GEMM_SMEM_BYTES);
    const dim3 gemm_grid(Dn / 128, (Bn * Sn) / 128);  // (8, 128)
    qkv_gemm_mma<<<gemm_grid, 256, GEMM_SMEM_BYTES>>>(X, Wq, bq, q);
    qkv_gemm_mma<<<gemm_grid, 256, GEMM_SMEM_BYTES>>>(X, Wk, bk, k);
    qkv_gemm_mma<<<gemm_grid, 256, GEMM_SMEM_BYTES>>>(X, Wv, bv, v);

    cudaFuncSetAttribute(attn_mma,
                         cudaFuncAttributeMaxDynamicSharedMemorySize, ATTN_SMEM_BYTES);
    const dim3 attn_grid(Sn / 128, Bn * Hn);          // (8, 256)
    attn_mma<<<attn_grid, 128, ATTN_SMEM_BYTES>>>(q, k, v, out);
}